// round 2
// baseline (speedup 1.0000x reference)
#include <cuda_runtime.h>
#include <cuda_bf16.h>

// Problem constants (from reference)
#define GH   2048
#define GW   2048
#define NPTS 1000000
#define EMBD 32
#define HID  64

__global__ __launch_bounds__(128)
void fused_mlp_kernel(
    const float* __restrict__ x,          // [N,2]
    const float* __restrict__ positions,  // [N_POS,2]
    const int*   __restrict__ nmap,       // [H,W,4]
    const float* __restrict__ emb,        // [N_POS,32]
    const float* __restrict__ W1,         // [64,32]
    const float* __restrict__ b1,         // [64]
    const float* __restrict__ W2,         // [64,64]
    const float* __restrict__ b2,         // [64]
    const float* __restrict__ W3,         // [3,64]
    const float* __restrict__ b3,         // [3]
    const float* __restrict__ mu,         // [3]
    const float* __restrict__ stdv,       // [3]
    float* __restrict__ out,              // [N,3]
    int n)
{
    // Weights staged in shared memory; W2 stored transposed so the inner
    // accumulation over output channel j2 is contiguous (float4 LDS, uniform
    // address -> broadcast, conflict-free).
    __shared__ float W1s[HID * EMBD];    // [j][d] row-major
    __shared__ float W2ts[HID * HID];    // [j][j2] = W2[j2][j]
    __shared__ float W3s[3 * HID];
    __shared__ float b1s[HID], b2s[HID];
    __shared__ float b3s[3], mus[3], stds[3];

    const int t = threadIdx.x;
    for (int i = t; i < HID * EMBD; i += blockDim.x) W1s[i] = W1[i];
    for (int i = t; i < HID * HID; i += blockDim.x) {
        int j2 = i / HID, j = i % HID;          // i indexes W2 row-major [j2][j]
        W2ts[j * HID + j2] = W2[i];
    }
    for (int i = t; i < 3 * HID; i += blockDim.x) W3s[i] = W3[i];
    if (t < HID) { b1s[t] = b1[t]; b2s[t] = b2[t]; }
    if (t < 3)   { b3s[t] = b3[t]; mus[t] = mu[t]; stds[t] = stdv[t]; }
    __syncthreads();

    const int i = blockIdx.x * blockDim.x + t;
    if (i >= n) return;

    // ---- gather + distance-weighted embedding reduction ----
    const float2 xy = ((const float2*)x)[i];
    const int ix = (int)floorf(xy.x);
    const int iy = (int)floorf(xy.y);
    const float fx = (float)ix, fy = (float)iy;

    const int4 nb = ((const int4*)nmap)[ix * GW + iy];
    const int nbk[4] = { nb.x, nb.y, nb.z, nb.w };

    float latent[EMBD];
    #pragma unroll
    for (int d = 0; d < EMBD; d++) latent[d] = 0.0f;

    #pragma unroll
    for (int k = 0; k < 4; k++) {
        const int idx = nbk[k];
        const float2 p = ((const float2*)positions)[idx];
        const float dx = p.x - fx;
        const float dy = p.y - fy;
        const float dist = sqrtf(dx * dx + dy * dy);
        const float4* e4 = (const float4*)(emb + (size_t)idx * EMBD);
        #pragma unroll
        for (int q = 0; q < EMBD / 4; q++) {
            const float4 e = e4[q];
            latent[q * 4 + 0] = fmaf(dist, e.x, latent[q * 4 + 0]);
            latent[q * 4 + 1] = fmaf(dist, e.y, latent[q * 4 + 1]);
            latent[q * 4 + 2] = fmaf(dist, e.z, latent[q * 4 + 2]);
            latent[q * 4 + 3] = fmaf(dist, e.w, latent[q * 4 + 3]);
        }
    }

    // ---- layer1 + layer2 fused: stream each h1[j], accumulate into h2 ----
    // Live registers: latent(32) + h2(64) + a scalar, instead of h1+h2 both.
    float h2[HID];
    #pragma unroll
    for (int j = 0; j < HID; j++) h2[j] = b2s[j];

    #pragma unroll 4
    for (int j = 0; j < HID; j++) {
        float s = b1s[j];
        const float4* w1 = (const float4*)(W1s + j * EMBD);
        #pragma unroll
        for (int q = 0; q < EMBD / 4; q++) {
            const float4 w = w1[q];
            s = fmaf(latent[q * 4 + 0], w.x, s);
            s = fmaf(latent[q * 4 + 1], w.y, s);
            s = fmaf(latent[q * 4 + 2], w.z, s);
            s = fmaf(latent[q * 4 + 3], w.w, s);
        }
        s = fmaxf(s, 0.0f);   // relu(h1[j])
        const float4* w2 = (const float4*)(W2ts + j * HID);
        #pragma unroll
        for (int q = 0; q < HID / 4; q++) {
            const float4 w = w2[q];
            h2[q * 4 + 0] = fmaf(s, w.x, h2[q * 4 + 0]);
            h2[q * 4 + 1] = fmaf(s, w.y, h2[q * 4 + 1]);
            h2[q * 4 + 2] = fmaf(s, w.z, h2[q * 4 + 2]);
            h2[q * 4 + 3] = fmaf(s, w.w, h2[q * 4 + 3]);
        }
    }

    // relu(h2)
    #pragma unroll
    for (int j = 0; j < HID; j++) h2[j] = fmaxf(h2[j], 0.0f);

    // ---- layer3 + affine + nan-guard + clip ----
    float o[3];
    #pragma unroll
    for (int c = 0; c < 3; c++) {
        float s = b3s[c];
        const float* w3 = W3s + c * HID;
        #pragma unroll
        for (int j = 0; j < HID; j++) s = fmaf(h2[j], w3[j], s);
        o[c] = s * stds[c] + mus[c];
    }

    const bool has_nan = (o[0] != o[0]) || (o[1] != o[1]) || (o[2] != o[2]);
    #pragma unroll
    for (int c = 0; c < 3; c++) {
        const float v = has_nan ? mus[c]
                                : fminf(fmaxf(o[c], 0.0f), 1.0f);
        out[i * 3 + c] = v;
    }
}

extern "C" void kernel_launch(void* const* d_in, const int* in_sizes, int n_in,
                              void* d_out, int out_size) {
    const float* x    = (const float*)d_in[0];
    const float* pos  = (const float*)d_in[1];
    const int*   nmap = (const int*)d_in[2];
    const float* emb  = (const float*)d_in[3];
    const float* W1   = (const float*)d_in[4];
    const float* b1   = (const float*)d_in[5];
    const float* W2   = (const float*)d_in[6];
    const float* b2   = (const float*)d_in[7];
    const float* W3   = (const float*)d_in[8];
    const float* b3   = (const float*)d_in[9];
    const float* mu   = (const float*)d_in[10];
    const float* stdv = (const float*)d_in[11];
    float* out = (float*)d_out;

    const int n = in_sizes[0] / 2;   // x is [N,2]
    const int block = 128;
    const int grid = (n + block - 1) / block;
    fused_mlp_kernel<<<grid, block>>>(x, pos, nmap, emb, W1, b1, W2, b2,
                                      W3, b3, mu, stdv, out, n);
}

// round 3
// speedup vs baseline: 1.3210x; 1.3210x over previous
#include <cuda_runtime.h>

#define GW    2048
#define EMBD  32
#define HID   64
#define TILE  128
#define PSTR  136   // padded row stride (floats) for staggered transposed tiles

typedef unsigned long long ull;

// packed fp32x2 FMA (Blackwell): d = a*b + c on two lanes, identical rounding to fmaf
__device__ __forceinline__ ull ffma2(ull a, ull b, ull c) {
    ull d;
    asm("fma.rn.f32x2 %0, %1, %2, %3;" : "=l"(d) : "l"(a), "l"(b), "l"(c));
    return d;
}
__device__ __forceinline__ ull pack2(float x, float y) {
    ull d; asm("mov.b64 %0, {%1, %2};" : "=l"(d) : "f"(x), "f"(y)); return d;
}
__device__ __forceinline__ float2 unpack2(ull v) {
    float2 r; asm("mov.b64 {%0, %1}, %2;" : "=f"(r.x), "=f"(r.y) : "l"(v)); return r;
}

struct __align__(16) SmemLayout {
    float W1s[EMBD * HID];    // [d][c]  (transposed W1)
    float W2s[HID * HID];     // [d][c]  (transposed W2)
    float W3s[3 * HID];       // row-major
    float b1s[HID];
    float b2s[HID];
    float b3s[4], mus[4], stds[4];
    float LATt[EMBD * PSTR];  // [d][pt_staggered]
    float H1t[HID * PSTR];    // [d][pt_staggered], relu'd
    float H2t[HID * PSTR];    // [c][pt_staggered], relu'd
};

__global__ __launch_bounds__(TILE)
void fused_tiled_kernel(
    const float* __restrict__ x, const float* __restrict__ positions,
    const int* __restrict__ nmap, const float* __restrict__ emb,
    const float* __restrict__ W1, const float* __restrict__ b1,
    const float* __restrict__ W2, const float* __restrict__ b2,
    const float* __restrict__ W3, const float* __restrict__ b3,
    const float* __restrict__ mu, const float* __restrict__ stdv,
    float* __restrict__ out, int n)
{
    extern __shared__ char smraw[];
    SmemLayout* sm = reinterpret_cast<SmemLayout*>(smraw);
    const int t    = threadIdx.x;
    const int base = blockIdx.x * TILE;
    const int i    = base + t;

    // ---- stage weights (transposed so inner dim is output-channel) ----
    for (int idx = t; idx < HID * EMBD; idx += TILE) {
        int c = idx / EMBD, d = idx % EMBD;
        sm->W1s[d * HID + c] = W1[idx];
    }
    for (int idx = t; idx < HID * HID; idx += TILE) {
        int c = idx / HID, d = idx % HID;
        sm->W2s[d * HID + c] = W2[idx];
    }
    for (int idx = t; idx < 3 * HID; idx += TILE) sm->W3s[idx] = W3[idx];
    if (t < HID) { sm->b1s[t] = b1[t]; sm->b2s[t] = b2[t]; }
    if (t < 3)   { sm->b3s[t] = b3[t]; sm->mus[t] = mu[t]; sm->stds[t] = stdv[t]; }

    // ---- Phase A: per-thread gather + distance-weighted latent ----
    float lat[EMBD];
    #pragma unroll
    for (int d = 0; d < EMBD; d++) lat[d] = 0.0f;

    if (i < n) {
        const float2 xy = ((const float2*)x)[i];
        const int ix = (int)floorf(xy.x);
        const int iy = (int)floorf(xy.y);
        const float fx = (float)ix, fy = (float)iy;
        const int4 nb = ((const int4*)nmap)[ix * GW + iy];
        const int nbk[4] = { nb.x, nb.y, nb.z, nb.w };
        #pragma unroll
        for (int k = 0; k < 4; k++) {
            const int idx = nbk[k];
            const float2 p = ((const float2*)positions)[idx];
            const float dx = p.x - fx;
            const float dy = p.y - fy;
            const float dist = sqrtf(dx * dx + dy * dy);
            const float4* e4 = (const float4*)(emb + (size_t)idx * EMBD);
            #pragma unroll
            for (int q = 0; q < EMBD / 4; q++) {
                const float4 e = e4[q];
                lat[4 * q + 0] = fmaf(dist, e.x, lat[4 * q + 0]);
                lat[4 * q + 1] = fmaf(dist, e.y, lat[4 * q + 1]);
                lat[4 * q + 2] = fmaf(dist, e.z, lat[4 * q + 2]);
                lat[4 * q + 3] = fmaf(dist, e.w, lat[4 * q + 3]);
            }
        }
    }

    // staggered physical point index: chunk pg (8 pts) placed at pg*8 + (pg>>2)*2
    // so the 16 chunk-reads of one row hit all 32 banks exactly once.
    const int tphys = t + ((t >> 5) << 1);
    #pragma unroll
    for (int d = 0; d < EMBD; d++) sm->LATt[d * PSTR + tphys] = lat[d];
    __syncthreads();

    // ---- thread tile: 8 points (one chunk) x 8 channels ----
    const int pg = t & 15;            // point group
    const int cg = t >> 4;            // channel group
    const int pbase = pg * 8 + ((pg >> 2) << 1);
    const int c0 = cg * 8;

    ull acc[4][8];   // [point-pair][channel]

    // ================= GEMM1: H1 = relu(LAT @ W1^T + b1) =================
    #pragma unroll
    for (int c = 0; c < 8; c++) {
        const float b = sm->b1s[c0 + c];
        const ull bb = pack2(b, b);
        acc[0][c] = bb; acc[1][c] = bb; acc[2][c] = bb; acc[3][c] = bb;
    }
    #pragma unroll 8
    for (int d = 0; d < EMBD; d++) {
        const float* lr = &sm->LATt[d * PSTR + pbase];
        const ull a0 = *(const ull*)(lr + 0);
        const ull a1 = *(const ull*)(lr + 2);
        const ull a2 = *(const ull*)(lr + 4);
        const ull a3 = *(const ull*)(lr + 6);
        const float* wr = &sm->W1s[d * HID + c0];
        const float4 w0 = *(const float4*)(wr);
        const float4 w1 = *(const float4*)(wr + 4);
        ull wd[8];
        wd[0] = pack2(w0.x, w0.x); wd[1] = pack2(w0.y, w0.y);
        wd[2] = pack2(w0.z, w0.z); wd[3] = pack2(w0.w, w0.w);
        wd[4] = pack2(w1.x, w1.x); wd[5] = pack2(w1.y, w1.y);
        wd[6] = pack2(w1.z, w1.z); wd[7] = pack2(w1.w, w1.w);
        #pragma unroll
        for (int c = 0; c < 8; c++) {
            acc[0][c] = ffma2(a0, wd[c], acc[0][c]);
            acc[1][c] = ffma2(a1, wd[c], acc[1][c]);
            acc[2][c] = ffma2(a2, wd[c], acc[2][c]);
            acc[3][c] = ffma2(a3, wd[c], acc[3][c]);
        }
    }
    #pragma unroll
    for (int c = 0; c < 8; c++) {
        float* hr = &sm->H1t[(c0 + c) * PSTR + pbase];
        #pragma unroll
        for (int p = 0; p < 4; p++) {
            float2 v = unpack2(acc[p][c]);
            v.x = fmaxf(v.x, 0.0f);
            v.y = fmaxf(v.y, 0.0f);
            *(float2*)(hr + 2 * p) = v;
        }
    }
    __syncthreads();

    // ================= GEMM2: H2 = relu(H1 @ W2^T + b2) =================
    #pragma unroll
    for (int c = 0; c < 8; c++) {
        const float b = sm->b2s[c0 + c];
        const ull bb = pack2(b, b);
        acc[0][c] = bb; acc[1][c] = bb; acc[2][c] = bb; acc[3][c] = bb;
    }
    #pragma unroll 8
    for (int d = 0; d < HID; d++) {
        const float* lr = &sm->H1t[d * PSTR + pbase];
        const ull a0 = *(const ull*)(lr + 0);
        const ull a1 = *(const ull*)(lr + 2);
        const ull a2 = *(const ull*)(lr + 4);
        const ull a3 = *(const ull*)(lr + 6);
        const float* wr = &sm->W2s[d * HID + c0];
        const float4 w0 = *(const float4*)(wr);
        const float4 w1 = *(const float4*)(wr + 4);
        ull wd[8];
        wd[0] = pack2(w0.x, w0.x); wd[1] = pack2(w0.y, w0.y);
        wd[2] = pack2(w0.z, w0.z); wd[3] = pack2(w0.w, w0.w);
        wd[4] = pack2(w1.x, w1.x); wd[5] = pack2(w1.y, w1.y);
        wd[6] = pack2(w1.z, w1.z); wd[7] = pack2(w1.w, w1.w);
        #pragma unroll
        for (int c = 0; c < 8; c++) {
            acc[0][c] = ffma2(a0, wd[c], acc[0][c]);
            acc[1][c] = ffma2(a1, wd[c], acc[1][c]);
            acc[2][c] = ffma2(a2, wd[c], acc[2][c]);
            acc[3][c] = ffma2(a3, wd[c], acc[3][c]);
        }
    }
    #pragma unroll
    for (int c = 0; c < 8; c++) {
        float* hr = &sm->H2t[(c0 + c) * PSTR + pbase];
        #pragma unroll
        for (int p = 0; p < 4; p++) {
            float2 v = unpack2(acc[p][c]);
            v.x = fmaxf(v.x, 0.0f);
            v.y = fmaxf(v.y, 0.0f);
            *(float2*)(hr + 2 * p) = v;
        }
    }
    __syncthreads();

    // ================= Phase D: out = clip((H2 @ W3^T + b3)*std + mu) ====
    if (i < n) {
        float s0 = sm->b3s[0], s1 = sm->b3s[1], s2 = sm->b3s[2];
        float u0 = 0.0f, u1 = 0.0f, u2 = 0.0f;
        #pragma unroll 8
        for (int c = 0; c < HID; c += 2) {
            const float h0 = sm->H2t[c * PSTR + tphys];
            const float h1 = sm->H2t[(c + 1) * PSTR + tphys];
            s0 = fmaf(h0, sm->W3s[0 * HID + c],     s0);
            u0 = fmaf(h1, sm->W3s[0 * HID + c + 1], u0);
            s1 = fmaf(h0, sm->W3s[1 * HID + c],     s1);
            u1 = fmaf(h1, sm->W3s[1 * HID + c + 1], u1);
            s2 = fmaf(h0, sm->W3s[2 * HID + c],     s2);
            u2 = fmaf(h1, sm->W3s[2 * HID + c + 1], u2);
        }
        float o[3];
        o[0] = (s0 + u0) * sm->stds[0] + sm->mus[0];
        o[1] = (s1 + u1) * sm->stds[1] + sm->mus[1];
        o[2] = (s2 + u2) * sm->stds[2] + sm->mus[2];
        const bool has_nan = (o[0] != o[0]) || (o[1] != o[1]) || (o[2] != o[2]);
        #pragma unroll
        for (int c = 0; c < 3; c++) {
            out[i * 3 + c] = has_nan ? sm->mus[c]
                                     : fminf(fmaxf(o[c], 0.0f), 1.0f);
        }
    }
}

extern "C" void kernel_launch(void* const* d_in, const int* in_sizes, int n_in,
                              void* d_out, int out_size) {
    const float* x    = (const float*)d_in[0];
    const float* pos  = (const float*)d_in[1];
    const int*   nmap = (const int*)d_in[2];
    const float* emb  = (const float*)d_in[3];
    const float* W1   = (const float*)d_in[4];
    const float* b1   = (const float*)d_in[5];
    const float* W2   = (const float*)d_in[6];
    const float* b2   = (const float*)d_in[7];
    const float* W3   = (const float*)d_in[8];
    const float* b3   = (const float*)d_in[9];
    const float* mu   = (const float*)d_in[10];
    const float* stdv = (const float*)d_in[11];
    float* out = (float*)d_out;

    const int n = in_sizes[0] / 2;   // x is [N,2]
    const int grid = (n + TILE - 1) / TILE;
    const int smem = (int)sizeof(SmemLayout);

    cudaFuncSetAttribute(fused_tiled_kernel,
                         cudaFuncAttributeMaxDynamicSharedMemorySize, smem);
    fused_tiled_kernel<<<grid, TILE, smem>>>(x, pos, nmap, emb, W1, b1, W2, b2,
                                             W3, b3, mu, stdv, out, n);
}

// round 4
// speedup vs baseline: 1.3252x; 1.0032x over previous
#include <cuda_runtime.h>

#define GW    2048
#define EMBD  32
#define HID   64
#define TILE  128
#define PSTR  136   // padded row stride (floats) for staggered transposed tiles

typedef unsigned long long ull;

// packed fp32x2 FMA (Blackwell): d = a*b + c on two lanes, identical rounding to fmaf
__device__ __forceinline__ ull ffma2(ull a, ull b, ull c) {
    ull d;
    asm("fma.rn.f32x2 %0, %1, %2, %3;" : "=l"(d) : "l"(a), "l"(b), "l"(c));
    return d;
}
__device__ __forceinline__ ull pack2(float x, float y) {
    ull d; asm("mov.b64 %0, {%1, %2};" : "=l"(d) : "f"(x), "f"(y)); return d;
}
__device__ __forceinline__ float2 unpack2(ull v) {
    float2 r; asm("mov.b64 {%0, %1}, %2;" : "=f"(r.x), "=f"(r.y) : "l"(v)); return r;
}

struct __align__(16) SmemLayout {
    float W1s[EMBD * HID];    // [d][c]  (transposed W1)
    float W2s[HID * HID];     // [d][c]  (transposed W2)
    float W3s[3 * HID];       // row-major
    float b1s[HID];
    float b2s[HID];
    float b3s[4], mus[4], stds[4];
    float LATt[EMBD * PSTR];  // [d][pt_staggered]
    float H1t[HID * PSTR];    // [d][pt_staggered], relu'd
    float H2t[HID * PSTR];    // [c][pt_staggered], relu'd
};

__global__ __launch_bounds__(TILE)
void fused_tiled_kernel(
    const float* __restrict__ x, const float* __restrict__ positions,
    const int* __restrict__ nmap, const float* __restrict__ emb,
    const float* __restrict__ W1, const float* __restrict__ b1,
    const float* __restrict__ W2, const float* __restrict__ b2,
    const float* __restrict__ W3, const float* __restrict__ b3,
    const float* __restrict__ mu, const float* __restrict__ stdv,
    float* __restrict__ out, int n)
{
    extern __shared__ char smraw[];
    SmemLayout* sm = reinterpret_cast<SmemLayout*>(smraw);
    const int t    = threadIdx.x;
    const int base = blockIdx.x * TILE;
    const int i    = base + t;

    // ---- stage weights (transposed so inner dim is output-channel) ----
    for (int idx = t; idx < HID * EMBD; idx += TILE) {
        int c = idx / EMBD, d = idx % EMBD;
        sm->W1s[d * HID + c] = W1[idx];
    }
    for (int idx = t; idx < HID * HID; idx += TILE) {
        int c = idx / HID, d = idx % HID;
        sm->W2s[d * HID + c] = W2[idx];
    }
    for (int idx = t; idx < 3 * HID; idx += TILE) sm->W3s[idx] = W3[idx];
    if (t < HID) { sm->b1s[t] = b1[t]; sm->b2s[t] = b2[t]; }
    if (t < 3)   { sm->b3s[t] = b3[t]; sm->mus[t] = mu[t]; sm->stds[t] = stdv[t]; }

    // ---- Phase A: per-thread gather + distance-weighted latent ----
    float lat[EMBD];
    #pragma unroll
    for (int d = 0; d < EMBD; d++) lat[d] = 0.0f;

    if (i < n) {
        const float2 xy = ((const float2*)x)[i];
        const int ix = (int)floorf(xy.x);
        const int iy = (int)floorf(xy.y);
        const float fx = (float)ix, fy = (float)iy;
        const int4 nb = ((const int4*)nmap)[ix * GW + iy];
        const int nbk[4] = { nb.x, nb.y, nb.z, nb.w };
        #pragma unroll
        for (int k = 0; k < 4; k++) {
            const int idx = nbk[k];
            const float2 p = ((const float2*)positions)[idx];
            const float dx = p.x - fx;
            const float dy = p.y - fy;
            const float dist = sqrtf(dx * dx + dy * dy);
            const float4* e4 = (const float4*)(emb + (size_t)idx * EMBD);
            #pragma unroll
            for (int q = 0; q < EMBD / 4; q++) {
                const float4 e = e4[q];
                lat[4 * q + 0] = fmaf(dist, e.x, lat[4 * q + 0]);
                lat[4 * q + 1] = fmaf(dist, e.y, lat[4 * q + 1]);
                lat[4 * q + 2] = fmaf(dist, e.z, lat[4 * q + 2]);
                lat[4 * q + 3] = fmaf(dist, e.w, lat[4 * q + 3]);
            }
        }
    }

    // staggered physical point index: chunk pg (8 pts) placed at pg*8 + (pg>>2)*2
    // so the 16 chunk-reads of one row hit all 32 banks exactly once.
    const int tphys = t + ((t >> 5) << 1);
    #pragma unroll
    for (int d = 0; d < EMBD; d++) sm->LATt[d * PSTR + tphys] = lat[d];
    __syncthreads();

    // ---- thread tile: 8 points (one chunk) x 8 channels ----
    const int pg = t & 15;            // point group
    const int cg = t >> 4;            // channel group
    const int pbase = pg * 8 + ((pg >> 2) << 1);
    const int c0 = cg * 8;

    ull acc[4][8];   // [point-pair][channel]

    // ================= GEMM1: H1 = relu(LAT @ W1^T + b1) =================
    #pragma unroll
    for (int c = 0; c < 8; c++) {
        const float b = sm->b1s[c0 + c];
        const ull bb = pack2(b, b);
        acc[0][c] = bb; acc[1][c] = bb; acc[2][c] = bb; acc[3][c] = bb;
    }
    #pragma unroll 8
    for (int d = 0; d < EMBD; d++) {
        const float* lr = &sm->LATt[d * PSTR + pbase];
        const ull a0 = *(const ull*)(lr + 0);
        const ull a1 = *(const ull*)(lr + 2);
        const ull a2 = *(const ull*)(lr + 4);
        const ull a3 = *(const ull*)(lr + 6);
        const float* wr = &sm->W1s[d * HID + c0];
        const float4 w0 = *(const float4*)(wr);
        const float4 w1 = *(const float4*)(wr + 4);
        ull wd[8];
        wd[0] = pack2(w0.x, w0.x); wd[1] = pack2(w0.y, w0.y);
        wd[2] = pack2(w0.z, w0.z); wd[3] = pack2(w0.w, w0.w);
        wd[4] = pack2(w1.x, w1.x); wd[5] = pack2(w1.y, w1.y);
        wd[6] = pack2(w1.z, w1.z); wd[7] = pack2(w1.w, w1.w);
        #pragma unroll
        for (int c = 0; c < 8; c++) {
            acc[0][c] = ffma2(a0, wd[c], acc[0][c]);
            acc[1][c] = ffma2(a1, wd[c], acc[1][c]);
            acc[2][c] = ffma2(a2, wd[c], acc[2][c]);
            acc[3][c] = ffma2(a3, wd[c], acc[3][c]);
        }
    }
    #pragma unroll
    for (int c = 0; c < 8; c++) {
        float* hr = &sm->H1t[(c0 + c) * PSTR + pbase];
        #pragma unroll
        for (int p = 0; p < 4; p++) {
            float2 v = unpack2(acc[p][c]);
            v.x = fmaxf(v.x, 0.0f);
            v.y = fmaxf(v.y, 0.0f);
            *(float2*)(hr + 2 * p) = v;
        }
    }
    __syncthreads();

    // ================= GEMM2: H2 = relu(H1 @ W2^T + b2) =================
    #pragma unroll
    for (int c = 0; c < 8; c++) {
        const float b = sm->b2s[c0 + c];
        const ull bb = pack2(b, b);
        acc[0][c] = bb; acc[1][c] = bb; acc[2][c] = bb; acc[3][c] = bb;
    }
    #pragma unroll 8
    for (int d = 0; d < HID; d++) {
        const float* lr = &sm->H1t[d * PSTR + pbase];
        const ull a0 = *(const ull*)(lr + 0);
        const ull a1 = *(const ull*)(lr + 2);
        const ull a2 = *(const ull*)(lr + 4);
        const ull a3 = *(const ull*)(lr + 6);
        const float* wr = &sm->W2s[d * HID + c0];
        const float4 w0 = *(const float4*)(wr);
        const float4 w1 = *(const float4*)(wr + 4);
        ull wd[8];
        wd[0] = pack2(w0.x, w0.x); wd[1] = pack2(w0.y, w0.y);
        wd[2] = pack2(w0.z, w0.z); wd[3] = pack2(w0.w, w0.w);
        wd[4] = pack2(w1.x, w1.x); wd[5] = pack2(w1.y, w1.y);
        wd[6] = pack2(w1.z, w1.z); wd[7] = pack2(w1.w, w1.w);
        #pragma unroll
        for (int c = 0; c < 8; c++) {
            acc[0][c] = ffma2(a0, wd[c], acc[0][c]);
            acc[1][c] = ffma2(a1, wd[c], acc[1][c]);
            acc[2][c] = ffma2(a2, wd[c], acc[2][c]);
            acc[3][c] = ffma2(a3, wd[c], acc[3][c]);
        }
    }
    #pragma unroll
    for (int c = 0; c < 8; c++) {
        float* hr = &sm->H2t[(c0 + c) * PSTR + pbase];
        #pragma unroll
        for (int p = 0; p < 4; p++) {
            float2 v = unpack2(acc[p][c]);
            v.x = fmaxf(v.x, 0.0f);
            v.y = fmaxf(v.y, 0.0f);
            *(float2*)(hr + 2 * p) = v;
        }
    }
    __syncthreads();

    // ================= Phase D: out = clip((H2 @ W3^T + b3)*std + mu) ====
    if (i < n) {
        float s0 = sm->b3s[0], s1 = sm->b3s[1], s2 = sm->b3s[2];
        float u0 = 0.0f, u1 = 0.0f, u2 = 0.0f;
        #pragma unroll 8
        for (int c = 0; c < HID; c += 2) {
            const float h0 = sm->H2t[c * PSTR + tphys];
            const float h1 = sm->H2t[(c + 1) * PSTR + tphys];
            s0 = fmaf(h0, sm->W3s[0 * HID + c],     s0);
            u0 = fmaf(h1, sm->W3s[0 * HID + c + 1], u0);
            s1 = fmaf(h0, sm->W3s[1 * HID + c],     s1);
            u1 = fmaf(h1, sm->W3s[1 * HID + c + 1], u1);
            s2 = fmaf(h0, sm->W3s[2 * HID + c],     s2);
            u2 = fmaf(h1, sm->W3s[2 * HID + c + 1], u2);
        }
        float o[3];
        o[0] = (s0 + u0) * sm->stds[0] + sm->mus[0];
        o[1] = (s1 + u1) * sm->stds[1] + sm->mus[1];
        o[2] = (s2 + u2) * sm->stds[2] + sm->mus[2];
        const bool has_nan = (o[0] != o[0]) || (o[1] != o[1]) || (o[2] != o[2]);
        #pragma unroll
        for (int c = 0; c < 3; c++) {
            out[i * 3 + c] = has_nan ? sm->mus[c]
                                     : fminf(fmaxf(o[c], 0.0f), 1.0f);
        }
    }
}

extern "C" void kernel_launch(void* const* d_in, const int* in_sizes, int n_in,
                              void* d_out, int out_size) {
    const float* x    = (const float*)d_in[0];
    const float* pos  = (const float*)d_in[1];
    const int*   nmap = (const int*)d_in[2];
    const float* emb  = (const float*)d_in[3];
    const float* W1   = (const float*)d_in[4];
    const float* b1   = (const float*)d_in[5];
    const float* W2   = (const float*)d_in[6];
    const float* b2   = (const float*)d_in[7];
    const float* W3   = (const float*)d_in[8];
    const float* b3   = (const float*)d_in[9];
    const float* mu   = (const float*)d_in[10];
    const float* stdv = (const float*)d_in[11];
    float* out = (float*)d_out;

    const int n = in_sizes[0] / 2;   // x is [N,2]
    const int grid = (n + TILE - 1) / TILE;
    const int smem = (int)sizeof(SmemLayout);

    cudaFuncSetAttribute(fused_tiled_kernel,
                         cudaFuncAttributeMaxDynamicSharedMemorySize, smem);
    fused_tiled_kernel<<<grid, TILE, smem>>>(x, pos, nmap, emb, W1, b1, W2, b2,
                                             W3, b3, mu, stdv, out, n);
}

// round 8
// speedup vs baseline: 1.4244x; 1.0749x over previous
#include <cuda_runtime.h>
#include <cstdint>

#define GW    2048
#define EMBD  32
#define HID   64
#define TPTS  256          // points per CTA
#define NTHR  256          // 8 warps
#define S1    36           // padded K-stride (floats) for K=32 tiles; 36%32==4 -> conflict-free quad reads
#define S2    68           // padded K-stride for K=64 tiles; 68%32==4

// ---- SMEM float-index offsets ----
#define F_W3    0            // 192
#define F_B1    192          // 64
#define F_B2    256          // 64
#define F_B3    320          // 3
#define F_MU    324          // 3
#define F_STD   328          // 3
#define F_W1HI  384          // 64*S1 = 2304
#define F_W1LO  (F_W1HI + 64*S1)
#define F_W2HI  (F_W1LO + 64*S1)            // 64*S2 = 4352
#define F_W2LO  (F_W2HI + 64*S2)
#define F_POOL  (F_W2LO + 64*S2)
#define F_LATHI (F_POOL)                    // 256*S1 = 9216
#define F_LATLO (F_POOL + TPTS*S1)
#define F_H1HI  (F_POOL)                    // overlays LAT (disjoint lifetime)
#define F_H1LO  (F_POOL + TPTS*S2)          // 256*S2 = 17408
#define SMEM_FLOATS (F_POOL + 2*TPTS*S2)
#define SMEM_BYTES  (SMEM_FLOATS * 4)       // 194048 B

typedef unsigned int u32;

__device__ __forceinline__ void split1(float a, float& hi, float& lo) {
    hi = __uint_as_float(__float_as_uint(a) & 0xFFFFE000u);   // exact tf32
    lo = a - hi;
}

__device__ __forceinline__ void mma_tf32(float c[4], const u32 a[4], const u32 b[2]) {
    asm volatile(
        "mma.sync.aligned.m16n8k8.row.col.f32.tf32.tf32.f32 "
        "{%0,%1,%2,%3}, {%4,%5,%6,%7}, {%8,%9}, {%0,%1,%2,%3};"
        : "+f"(c[0]), "+f"(c[1]), "+f"(c[2]), "+f"(c[3])
        : "r"(a[0]), "r"(a[1]), "r"(a[2]), "r"(a[3]), "r"(b[0]), "r"(b[1]));
}

// One warp computes rows [mrow, mrow+32) x all 64 cols, K = NK*8, 3xTF32.
template<int S, int NK>
__device__ __forceinline__ void warp_gemm3(
    const float* __restrict__ Ahi, const float* __restrict__ Alo,
    const float* __restrict__ Bhi, const float* __restrict__ Blo,
    float (&c)[2][8][4], int mrow, int g, int tq)
{
    #pragma unroll
    for (int ks = 0; ks < NK; ks++) {
        const int k0 = ks * 8;
        u32 ahi[2][4], alo[2][4];
        #pragma unroll
        for (int mt = 0; mt < 2; mt++) {
            const int r = mrow + mt * 16 + g;
            const float* Ah = Ahi + r * S + k0 + tq;
            const float* Al = Alo + r * S + k0 + tq;
            ahi[mt][0] = __float_as_uint(Ah[0]);
            ahi[mt][1] = __float_as_uint(Ah[8 * S]);
            ahi[mt][2] = __float_as_uint(Ah[4]);
            ahi[mt][3] = __float_as_uint(Ah[8 * S + 4]);
            alo[mt][0] = __float_as_uint(Al[0]);
            alo[mt][1] = __float_as_uint(Al[8 * S]);
            alo[mt][2] = __float_as_uint(Al[4]);
            alo[mt][3] = __float_as_uint(Al[8 * S + 4]);
        }
        #pragma unroll
        for (int nt = 0; nt < 8; nt++) {
            const int nb = (nt * 8 + g) * S + k0 + tq;
            u32 bhi[2] = { __float_as_uint(Bhi[nb]), __float_as_uint(Bhi[nb + 4]) };
            u32 blo[2] = { __float_as_uint(Blo[nb]), __float_as_uint(Blo[nb + 4]) };
            #pragma unroll
            for (int mt = 0; mt < 2; mt++) {
                mma_tf32(c[mt][nt], ahi[mt], bhi);   // hi*hi
                mma_tf32(c[mt][nt], ahi[mt], blo);   // hi*lo
                mma_tf32(c[mt][nt], alo[mt], bhi);   // lo*hi
            }
        }
    }
}

__global__ __launch_bounds__(NTHR)
void fused_mma_kernel(
    const float* __restrict__ x, const float* __restrict__ positions,
    const int* __restrict__ nmap, const float* __restrict__ emb,
    const float* __restrict__ W1, const float* __restrict__ b1,
    const float* __restrict__ W2, const float* __restrict__ b2,
    const float* __restrict__ W3, const float* __restrict__ b3,
    const float* __restrict__ mu, const float* __restrict__ stdv,
    float* __restrict__ out, int n)
{
    extern __shared__ float sp[];
    const int t    = threadIdx.x;
    const int lane = t & 31;
    const int wid  = t >> 5;
    const int g    = lane >> 2;       // group id (0..7)
    const int tq   = lane & 3;        // thread-in-group (0..3)
    const int mrow = wid * 32;        // this warp's row base in the CTA tile
    const int base = blockIdx.x * TPTS;
    const int i    = base + t;

    // ---- stage weights (split tf32 hi/lo, K-padded) ----
    for (int idx = t; idx < HID * EMBD; idx += NTHR) {     // W1 [64,32]
        const int no = idx >> 5, k = idx & 31;
        float hi, lo; split1(W1[idx], hi, lo);
        sp[F_W1HI + no * S1 + k] = hi;
        sp[F_W1LO + no * S1 + k] = lo;
    }
    for (int idx = t; idx < HID * HID; idx += NTHR) {      // W2 [64,64]
        const int no = idx >> 6, k = idx & 63;
        float hi, lo; split1(W2[idx], hi, lo);
        sp[F_W2HI + no * S2 + k] = hi;
        sp[F_W2LO + no * S2 + k] = lo;
    }
    for (int idx = t; idx < 3 * HID; idx += NTHR) sp[F_W3 + idx] = W3[idx];
    if (t < HID) { sp[F_B1 + t] = b1[t]; sp[F_B2 + t] = b2[t]; }
    if (t < 3)   { sp[F_B3 + t] = b3[t]; sp[F_MU + t] = mu[t]; sp[F_STD + t] = stdv[t]; }

    // ---- Phase A: gather + distance-weighted latent ----
    float lat[EMBD];
    #pragma unroll
    for (int d = 0; d < EMBD; d++) lat[d] = 0.0f;
    if (i < n) {
        const float2 xy = ((const float2*)x)[i];
        const int ix = (int)floorf(xy.x);
        const int iy = (int)floorf(xy.y);
        const float fx = (float)ix, fy = (float)iy;
        const int4 nb = ((const int4*)nmap)[ix * GW + iy];
        const int nbk[4] = { nb.x, nb.y, nb.z, nb.w };
        #pragma unroll
        for (int k = 0; k < 4; k++) {
            const int idx = nbk[k];
            const float2 p = ((const float2*)positions)[idx];
            const float dx = p.x - fx, dy = p.y - fy;
            const float dist = sqrtf(dx * dx + dy * dy);
            const float4* e4 = (const float4*)(emb + (size_t)idx * EMBD);
            #pragma unroll
            for (int q = 0; q < EMBD / 4; q++) {
                const float4 e = e4[q];
                lat[4*q+0] = fmaf(dist, e.x, lat[4*q+0]);
                lat[4*q+1] = fmaf(dist, e.y, lat[4*q+1]);
                lat[4*q+2] = fmaf(dist, e.z, lat[4*q+2]);
                lat[4*q+3] = fmaf(dist, e.w, lat[4*q+3]);
            }
        }
    }
    // store LAT hi/lo row t (float4, 16B aligned: t*S1*4 = 144t)
    #pragma unroll
    for (int q = 0; q < EMBD / 4; q++) {
        float4 h, l;
        split1(lat[4*q+0], h.x, l.x); split1(lat[4*q+1], h.y, l.y);
        split1(lat[4*q+2], h.z, l.z); split1(lat[4*q+3], h.w, l.w);
        *(float4*)&sp[F_LATHI + t * S1 + 4 * q] = h;
        *(float4*)&sp[F_LATLO + t * S1 + 4 * q] = l;
    }
    __syncthreads();

    // ---- GEMM1: D1 = LAT @ W1^T ----
    float c[2][8][4];
    #pragma unroll
    for (int mt = 0; mt < 2; mt++)
        #pragma unroll
        for (int nt = 0; nt < 8; nt++)
            #pragma unroll
            for (int e = 0; e < 4; e++) c[mt][nt][e] = 0.0f;

    warp_gemm3<S1, 4>(&sp[F_LATHI], &sp[F_LATLO], &sp[F_W1HI], &sp[F_W1LO],
                      c, mrow, g, tq);
    __syncthreads();   // all LAT reads done before H1 overlays the pool

    // ---- epilogue1: H1 = relu(D1 + b1), split, store ----
    #pragma unroll
    for (int nt = 0; nt < 8; nt++) {
        const int c0 = nt * 8 + 2 * tq;
        const float bc0 = sp[F_B1 + c0], bc1 = sp[F_B1 + c0 + 1];
        #pragma unroll
        for (int mt = 0; mt < 2; mt++) {
            const int r0 = mrow + mt * 16 + g, r1 = r0 + 8;
            float h00, l00, h01, l01, h10, l10, h11, l11;
            split1(fmaxf(c[mt][nt][0] + bc0, 0.0f), h00, l00);
            split1(fmaxf(c[mt][nt][1] + bc1, 0.0f), h01, l01);
            split1(fmaxf(c[mt][nt][2] + bc0, 0.0f), h10, l10);
            split1(fmaxf(c[mt][nt][3] + bc1, 0.0f), h11, l11);
            *(float2*)&sp[F_H1HI + r0 * S2 + c0] = make_float2(h00, h01);
            *(float2*)&sp[F_H1LO + r0 * S2 + c0] = make_float2(l00, l01);
            *(float2*)&sp[F_H1HI + r1 * S2 + c0] = make_float2(h10, h11);
            *(float2*)&sp[F_H1LO + r1 * S2 + c0] = make_float2(l10, l11);
        }
    }
    __syncthreads();

    // ---- GEMM2: D2 = H1 @ W2^T ----
    #pragma unroll
    for (int mt = 0; mt < 2; mt++)
        #pragma unroll
        for (int nt = 0; nt < 8; nt++)
            #pragma unroll
            for (int e = 0; e < 4; e++) c[mt][nt][e] = 0.0f;

    warp_gemm3<S2, 8>(&sp[F_H1HI], &sp[F_H1LO], &sp[F_W2HI], &sp[F_W2LO],
                      c, mrow, g, tq);

    // ---- epilogue2: h2 = relu(D2+b2); layer3 partials; quad-reduce; output ----
    float a3[2][2][3];   // [mt][rowhalf][ch]
    #pragma unroll
    for (int mt = 0; mt < 2; mt++)
        #pragma unroll
        for (int rh = 0; rh < 2; rh++)
            #pragma unroll
            for (int ch = 0; ch < 3; ch++) a3[mt][rh][ch] = 0.0f;

    #pragma unroll
    for (int nt = 0; nt < 8; nt++) {
        const int c0 = nt * 8 + 2 * tq;
        const float bc0 = sp[F_B2 + c0], bc1 = sp[F_B2 + c0 + 1];
        float w30 = sp[F_W3 + 0 * HID + c0], w31 = sp[F_W3 + 0 * HID + c0 + 1];
        float w40 = sp[F_W3 + 1 * HID + c0], w41 = sp[F_W3 + 1 * HID + c0 + 1];
        float w50 = sp[F_W3 + 2 * HID + c0], w51 = sp[F_W3 + 2 * HID + c0 + 1];
        #pragma unroll
        for (int mt = 0; mt < 2; mt++) {
            const float h00 = fmaxf(c[mt][nt][0] + bc0, 0.0f);
            const float h01 = fmaxf(c[mt][nt][1] + bc1, 0.0f);
            const float h10 = fmaxf(c[mt][nt][2] + bc0, 0.0f);
            const float h11 = fmaxf(c[mt][nt][3] + bc1, 0.0f);
            a3[mt][0][0] = fmaf(h00, w30, fmaf(h01, w31, a3[mt][0][0]));
            a3[mt][0][1] = fmaf(h00, w40, fmaf(h01, w41, a3[mt][0][1]));
            a3[mt][0][2] = fmaf(h00, w50, fmaf(h01, w51, a3[mt][0][2]));
            a3[mt][1][0] = fmaf(h10, w30, fmaf(h11, w31, a3[mt][1][0]));
            a3[mt][1][1] = fmaf(h10, w40, fmaf(h11, w41, a3[mt][1][1]));
            a3[mt][1][2] = fmaf(h10, w50, fmaf(h11, w51, a3[mt][1][2]));
        }
    }
    // quad reduction over tq (lanes xor 1, xor 2)
    #pragma unroll
    for (int mt = 0; mt < 2; mt++)
        #pragma unroll
        for (int rh = 0; rh < 2; rh++)
            #pragma unroll
            for (int ch = 0; ch < 3; ch++) {
                float v = a3[mt][rh][ch];
                v += __shfl_xor_sync(0xFFFFFFFFu, v, 1);
                v += __shfl_xor_sync(0xFFFFFFFFu, v, 2);
                a3[mt][rh][ch] = v;
            }

    if (tq == 0) {
        const float mu0 = sp[F_MU + 0], mu1 = sp[F_MU + 1], mu2 = sp[F_MU + 2];
        const float sd0 = sp[F_STD + 0], sd1 = sp[F_STD + 1], sd2 = sp[F_STD + 2];
        const float bb0 = sp[F_B3 + 0], bb1 = sp[F_B3 + 1], bb2 = sp[F_B3 + 2];
        #pragma unroll
        for (int mt = 0; mt < 2; mt++)
            #pragma unroll
            for (int rh = 0; rh < 2; rh++) {
                const int row = mrow + mt * 16 + rh * 8 + g;
                const int pi = base + row;
                if (pi < n) {
                    const float o0 = (a3[mt][rh][0] + bb0) * sd0 + mu0;
                    const float o1 = (a3[mt][rh][1] + bb1) * sd1 + mu1;
                    const float o2 = (a3[mt][rh][2] + bb2) * sd2 + mu2;
                    const bool has_nan = (o0 != o0) || (o1 != o1) || (o2 != o2);
                    out[pi * 3 + 0] = has_nan ? mu0 : fminf(fmaxf(o0, 0.0f), 1.0f);
                    out[pi * 3 + 1] = has_nan ? mu1 : fminf(fmaxf(o1, 0.0f), 1.0f);
                    out[pi * 3 + 2] = has_nan ? mu2 : fminf(fmaxf(o2, 0.0f), 1.0f);
                }
            }
    }
}

extern "C" void kernel_launch(void* const* d_in, const int* in_sizes, int n_in,
                              void* d_out, int out_size) {
    const float* x    = (const float*)d_in[0];
    const float* pos  = (const float*)d_in[1];
    const int*   nmap = (const int*)d_in[2];
    const float* emb  = (const float*)d_in[3];
    const float* W1   = (const float*)d_in[4];
    const float* b1   = (const float*)d_in[5];
    const float* W2   = (const float*)d_in[6];
    const float* b2   = (const float*)d_in[7];
    const float* W3   = (const float*)d_in[8];
    const float* b3   = (const float*)d_in[9];
    const float* mu   = (const float*)d_in[10];
    const float* stdv = (const float*)d_in[11];
    float* out = (float*)d_out;

    const int n = in_sizes[0] / 2;
    const int grid = (n + TPTS - 1) / TPTS;
    cudaFuncSetAttribute(fused_mma_kernel,
                         cudaFuncAttributeMaxDynamicSharedMemorySize, SMEM_BYTES);
    fused_mma_kernel<<<grid, NTHR, SMEM_BYTES>>>(x, pos, nmap, emb, W1, b1, W2, b2,
                                                 W3, b3, mu, stdv, out, n);
}

// round 9
// speedup vs baseline: 2.4197x; 1.6987x over previous
#include <cuda_runtime.h>
#include <cuda_bf16.h>
#include <cstdint>

#define GW    2048
#define EMBD  32
#define HID   64
#define TPTS  256          // points per CTA
#define NTHR  256          // 8 warps
#define SA1   20           // u32 stride for K=32 tiles (16 used + pad); 20%32==20, g*20 residues distinct
#define SA2   36           // u32 stride for K=64 tiles (32 used + pad); 36%32==4

// ---- SMEM offsets in 4-byte units ----
#define F_W3    0                     // 192 floats
#define F_B1    192
#define F_B2    256
#define F_B3    320
#define F_MU    324
#define F_STD   328
#define U_W1HI  352                   // 64*SA1 = 1280 u32
#define U_W1LO  (U_W1HI + 64*SA1)
#define U_W2HI  (U_W1LO + 64*SA1)     // 64*SA2 = 2304 u32
#define U_W2LO  (U_W2HI + 64*SA2)
#define U_POOL  (U_W2LO + 64*SA2)     // 16B aligned (7520*4)
#define U_LATHI (U_POOL)              // 256*SA1 = 5120
#define U_LATLO (U_POOL + TPTS*SA1)
#define U_H1HI  (U_POOL)              // overlays LAT (disjoint lifetime)
#define U_H1LO  (U_POOL + TPTS*SA2)   // 256*SA2 = 9216
#define SMEM_WORDS (U_POOL + 2*TPTS*SA2)
#define SMEM_BYTES (SMEM_WORDS * 4)   // 103808 B -> 2 CTAs/SM

typedef unsigned int u32;

__device__ __forceinline__ void split_bf(float v, __nv_bfloat16& hi, __nv_bfloat16& lo) {
    hi = __float2bfloat16_rn(v);
    lo = __float2bfloat16_rn(v - __bfloat162float(hi));
}
__device__ __forceinline__ u32 pack_bf2(__nv_bfloat16 lo16, __nv_bfloat16 hi16) {
    __nv_bfloat162 p = __nv_bfloat162(lo16, hi16);   // .x -> low 16 bits (lower k)
    return *(u32*)&p;
}

__device__ __forceinline__ void mma_bf16(float c[4], const u32 a[4], const u32 b[2]) {
    asm volatile(
        "mma.sync.aligned.m16n8k16.row.col.f32.bf16.bf16.f32 "
        "{%0,%1,%2,%3}, {%4,%5,%6,%7}, {%8,%9}, {%0,%1,%2,%3};"
        : "+f"(c[0]), "+f"(c[1]), "+f"(c[2]), "+f"(c[3])
        : "r"(a[0]), "r"(a[1]), "r"(a[2]), "r"(a[3]), "r"(b[0]), "r"(b[1]));
}

// One warp: rows [mrow,mrow+32) x 64 cols. K = NK*16 (u32 cols = NK*8).
// 3 products: Ahi*Bhi + Ahi*Blo + Alo*Bhi  (lo*lo dropped, ~2^-16 rel)
template<int S, int NK>
__device__ __forceinline__ void warp_gemm_bf(
    const u32* __restrict__ Ahi, const u32* __restrict__ Alo,
    const u32* __restrict__ Bhi, const u32* __restrict__ Blo,
    float (&c)[2][8][4], int mrow, int g, int tq)
{
    #pragma unroll
    for (int ks = 0; ks < NK; ks++) {
        const int k0 = ks * 8;
        u32 ah[2][4], al[2][4];
        #pragma unroll
        for (int mt = 0; mt < 2; mt++) {
            const int r0 = (mrow + mt * 16 + g) * S + k0 + tq;
            const int r1 = r0 + 8 * S;
            ah[mt][0] = Ahi[r0];     ah[mt][1] = Ahi[r1];
            ah[mt][2] = Ahi[r0 + 4]; ah[mt][3] = Ahi[r1 + 4];
            al[mt][0] = Alo[r0];     al[mt][1] = Alo[r1];
            al[mt][2] = Alo[r0 + 4]; al[mt][3] = Alo[r1 + 4];
        }
        #pragma unroll
        for (int nt = 0; nt < 8; nt++) {
            const int nb = (nt * 8 + g) * S + k0 + tq;
            const u32 bh[2] = { Bhi[nb], Bhi[nb + 4] };
            const u32 bl[2] = { Blo[nb], Blo[nb + 4] };
            #pragma unroll
            for (int mt = 0; mt < 2; mt++) {
                mma_bf16(c[mt][nt], ah[mt], bh);
                mma_bf16(c[mt][nt], ah[mt], bl);
                mma_bf16(c[mt][nt], al[mt], bh);
            }
        }
    }
}

__global__ __launch_bounds__(NTHR)
void fused_bf16_kernel(
    const float* __restrict__ x, const float* __restrict__ positions,
    const int* __restrict__ nmap, const float* __restrict__ emb,
    const float* __restrict__ W1, const float* __restrict__ b1,
    const float* __restrict__ W2, const float* __restrict__ b2,
    const float* __restrict__ W3, const float* __restrict__ b3,
    const float* __restrict__ mu, const float* __restrict__ stdv,
    float* __restrict__ out, int n)
{
    extern __shared__ float sp[];
    u32* spu = (u32*)sp;
    const int t    = threadIdx.x;
    const int lane = t & 31;
    const int wid  = t >> 5;
    const int g    = lane >> 2;
    const int tq   = lane & 3;
    const int mrow = wid * 32;
    const int base = blockIdx.x * TPTS;
    const int i    = base + t;

    // ---- stage W1 [64,32] as packed bf16x2 hi/lo ----
    for (int idx = t; idx < 64 * 16; idx += NTHR) {
        const int no = idx >> 4, k2 = idx & 15;
        __nv_bfloat16 h0, l0, h1, l1;
        split_bf(W1[no * 32 + 2 * k2],     h0, l0);
        split_bf(W1[no * 32 + 2 * k2 + 1], h1, l1);
        spu[U_W1HI + no * SA1 + k2] = pack_bf2(h0, h1);
        spu[U_W1LO + no * SA1 + k2] = pack_bf2(l0, l1);
    }
    // ---- stage W2 [64,64] ----
    for (int idx = t; idx < 64 * 32; idx += NTHR) {
        const int no = idx >> 5, k2 = idx & 31;
        __nv_bfloat16 h0, l0, h1, l1;
        split_bf(W2[no * 64 + 2 * k2],     h0, l0);
        split_bf(W2[no * 64 + 2 * k2 + 1], h1, l1);
        spu[U_W2HI + no * SA2 + k2] = pack_bf2(h0, h1);
        spu[U_W2LO + no * SA2 + k2] = pack_bf2(l0, l1);
    }
    for (int idx = t; idx < 3 * HID; idx += NTHR) sp[F_W3 + idx] = W3[idx];
    if (t < HID) { sp[F_B1 + t] = b1[t]; sp[F_B2 + t] = b2[t]; }
    if (t < 3)   { sp[F_B3 + t] = b3[t]; sp[F_MU + t] = mu[t]; sp[F_STD + t] = stdv[t]; }

    // ---- Phase A: gather + distance-weighted latent ----
    float lat[EMBD];
    #pragma unroll
    for (int d = 0; d < EMBD; d++) lat[d] = 0.0f;
    if (i < n) {
        const float2 xy = ((const float2*)x)[i];
        const int ix = (int)floorf(xy.x);
        const int iy = (int)floorf(xy.y);
        const float fx = (float)ix, fy = (float)iy;
        const int4 nb = ((const int4*)nmap)[ix * GW + iy];
        const int nbk[4] = { nb.x, nb.y, nb.z, nb.w };
        #pragma unroll
        for (int k = 0; k < 4; k++) {
            const int idx = nbk[k];
            const float2 p = ((const float2*)positions)[idx];
            const float dx = p.x - fx, dy = p.y - fy;
            const float dist = sqrtf(dx * dx + dy * dy);
            const float4* e4 = (const float4*)(emb + (size_t)idx * EMBD);
            #pragma unroll
            for (int q = 0; q < EMBD / 4; q++) {
                const float4 e = e4[q];
                lat[4*q+0] = fmaf(dist, e.x, lat[4*q+0]);
                lat[4*q+1] = fmaf(dist, e.y, lat[4*q+1]);
                lat[4*q+2] = fmaf(dist, e.z, lat[4*q+2]);
                lat[4*q+3] = fmaf(dist, e.w, lat[4*q+3]);
            }
        }
    }
    // store LAT row t: 16 u32 hi + 16 u32 lo
    #pragma unroll
    for (int k2 = 0; k2 < 16; k2++) {
        __nv_bfloat16 h0, l0, h1, l1;
        split_bf(lat[2 * k2],     h0, l0);
        split_bf(lat[2 * k2 + 1], h1, l1);
        spu[U_LATHI + t * SA1 + k2] = pack_bf2(h0, h1);
        spu[U_LATLO + t * SA1 + k2] = pack_bf2(l0, l1);
    }
    __syncthreads();

    // ---- GEMM1: D1 = LAT @ W1^T ----
    float c[2][8][4];
    #pragma unroll
    for (int mt = 0; mt < 2; mt++)
        #pragma unroll
        for (int nt = 0; nt < 8; nt++)
            #pragma unroll
            for (int e = 0; e < 4; e++) c[mt][nt][e] = 0.0f;

    warp_gemm_bf<SA1, 2>(&spu[U_LATHI], &spu[U_LATLO], &spu[U_W1HI], &spu[U_W1LO],
                         c, mrow, g, tq);
    __syncthreads();   // LAT reads done before H1 overlays the pool

    // ---- epilogue1: H1 = relu(D1 + b1) -> split bf16 -> packed store ----
    #pragma unroll
    for (int nt = 0; nt < 8; nt++) {
        const int c0 = nt * 8 + 2 * tq;         // even col; pair (c0, c0+1)
        const int kc = nt * 4 + tq;             // u32 col in H1 rows
        const float bc0 = sp[F_B1 + c0], bc1 = sp[F_B1 + c0 + 1];
        #pragma unroll
        for (int mt = 0; mt < 2; mt++) {
            const int r0 = mrow + mt * 16 + g, r1 = r0 + 8;
            __nv_bfloat16 h0, l0, h1, l1;
            split_bf(fmaxf(c[mt][nt][0] + bc0, 0.0f), h0, l0);
            split_bf(fmaxf(c[mt][nt][1] + bc1, 0.0f), h1, l1);
            spu[U_H1HI + r0 * SA2 + kc] = pack_bf2(h0, h1);
            spu[U_H1LO + r0 * SA2 + kc] = pack_bf2(l0, l1);
            split_bf(fmaxf(c[mt][nt][2] + bc0, 0.0f), h0, l0);
            split_bf(fmaxf(c[mt][nt][3] + bc1, 0.0f), h1, l1);
            spu[U_H1HI + r1 * SA2 + kc] = pack_bf2(h0, h1);
            spu[U_H1LO + r1 * SA2 + kc] = pack_bf2(l0, l1);
        }
    }
    __syncthreads();

    // ---- GEMM2: D2 = H1 @ W2^T ----
    #pragma unroll
    for (int mt = 0; mt < 2; mt++)
        #pragma unroll
        for (int nt = 0; nt < 8; nt++)
            #pragma unroll
            for (int e = 0; e < 4; e++) c[mt][nt][e] = 0.0f;

    warp_gemm_bf<SA2, 4>(&spu[U_H1HI], &spu[U_H1LO], &spu[U_W2HI], &spu[U_W2LO],
                         c, mrow, g, tq);

    // ---- epilogue2: relu + layer3 partials + quad reduce + output ----
    float a3[2][2][3];
    #pragma unroll
    for (int mt = 0; mt < 2; mt++)
        #pragma unroll
        for (int rh = 0; rh < 2; rh++)
            #pragma unroll
            for (int ch = 0; ch < 3; ch++) a3[mt][rh][ch] = 0.0f;

    #pragma unroll
    for (int nt = 0; nt < 8; nt++) {
        const int c0 = nt * 8 + 2 * tq;
        const float bc0 = sp[F_B2 + c0], bc1 = sp[F_B2 + c0 + 1];
        const float w30 = sp[F_W3 + 0*HID + c0], w31 = sp[F_W3 + 0*HID + c0 + 1];
        const float w40 = sp[F_W3 + 1*HID + c0], w41 = sp[F_W3 + 1*HID + c0 + 1];
        const float w50 = sp[F_W3 + 2*HID + c0], w51 = sp[F_W3 + 2*HID + c0 + 1];
        #pragma unroll
        for (int mt = 0; mt < 2; mt++) {
            const float h00 = fmaxf(c[mt][nt][0] + bc0, 0.0f);
            const float h01 = fmaxf(c[mt][nt][1] + bc1, 0.0f);
            const float h10 = fmaxf(c[mt][nt][2] + bc0, 0.0f);
            const float h11 = fmaxf(c[mt][nt][3] + bc1, 0.0f);
            a3[mt][0][0] = fmaf(h00, w30, fmaf(h01, w31, a3[mt][0][0]));
            a3[mt][0][1] = fmaf(h00, w40, fmaf(h01, w41, a3[mt][0][1]));
            a3[mt][0][2] = fmaf(h00, w50, fmaf(h01, w51, a3[mt][0][2]));
            a3[mt][1][0] = fmaf(h10, w30, fmaf(h11, w31, a3[mt][1][0]));
            a3[mt][1][1] = fmaf(h10, w40, fmaf(h11, w41, a3[mt][1][1]));
            a3[mt][1][2] = fmaf(h10, w50, fmaf(h11, w51, a3[mt][1][2]));
        }
    }
    #pragma unroll
    for (int mt = 0; mt < 2; mt++)
        #pragma unroll
        for (int rh = 0; rh < 2; rh++)
            #pragma unroll
            for (int ch = 0; ch < 3; ch++) {
                float v = a3[mt][rh][ch];
                v += __shfl_xor_sync(0xFFFFFFFFu, v, 1);
                v += __shfl_xor_sync(0xFFFFFFFFu, v, 2);
                a3[mt][rh][ch] = v;
            }

    if (tq == 0) {
        const float mu0 = sp[F_MU+0], mu1 = sp[F_MU+1], mu2 = sp[F_MU+2];
        const float sd0 = sp[F_STD+0], sd1 = sp[F_STD+1], sd2 = sp[F_STD+2];
        const float bb0 = sp[F_B3+0], bb1 = sp[F_B3+1], bb2 = sp[F_B3+2];
        #pragma unroll
        for (int mt = 0; mt < 2; mt++)
            #pragma unroll
            for (int rh = 0; rh < 2; rh++) {
                const int pi = base + mrow + mt * 16 + rh * 8 + g;
                if (pi < n) {
                    const float o0 = (a3[mt][rh][0] + bb0) * sd0 + mu0;
                    const float o1 = (a3[mt][rh][1] + bb1) * sd1 + mu1;
                    const float o2 = (a3[mt][rh][2] + bb2) * sd2 + mu2;
                    const bool has_nan = (o0 != o0) || (o1 != o1) || (o2 != o2);
                    out[pi * 3 + 0] = has_nan ? mu0 : fminf(fmaxf(o0, 0.0f), 1.0f);
                    out[pi * 3 + 1] = has_nan ? mu1 : fminf(fmaxf(o1, 0.0f), 1.0f);
                    out[pi * 3 + 2] = has_nan ? mu2 : fminf(fmaxf(o2, 0.0f), 1.0f);
                }
            }
    }
}

extern "C" void kernel_launch(void* const* d_in, const int* in_sizes, int n_in,
                              void* d_out, int out_size) {
    const float* x    = (const float*)d_in[0];
    const float* pos  = (const float*)d_in[1];
    const int*   nmap = (const int*)d_in[2];
    const float* emb  = (const float*)d_in[3];
    const float* W1   = (const float*)d_in[4];
    const float* b1   = (const float*)d_in[5];
    const float* W2   = (const float*)d_in[6];
    const float* b2   = (const float*)d_in[7];
    const float* W3   = (const float*)d_in[8];
    const float* b3   = (const float*)d_in[9];
    const float* mu   = (const float*)d_in[10];
    const float* stdv = (const float*)d_in[11];
    float* out = (float*)d_out;

    const int n = in_sizes[0] / 2;
    const int grid = (n + TPTS - 1) / TPTS;
    cudaFuncSetAttribute(fused_bf16_kernel,
                         cudaFuncAttributeMaxDynamicSharedMemorySize, SMEM_BYTES);
    fused_bf16_kernel<<<grid, NTHR, SMEM_BYTES>>>(x, pos, nmap, emb, W1, b1, W2, b2,
                                                  W3, b3, mu, stdv, out, n);
}